// round 8
// baseline (speedup 1.0000x reference)
#include <cuda_runtime.h>
#include <cuda_bf16.h>

#define NBINS 256
#define NCH 3
#define NHIST (NBINS * NCH)     // 768
#define NCOL 16                 // sub-warp columns: lane & 15 -> private-ish column
#define BLOCK_THREADS 256
#define GRID_BLOCKS 591         // 591*256 = 151296, divisible by 3 AND by 32
// stride % 3 == 0  ->  each thread's channel phase is loop-invariant.

// Zero at module load; the fused last-block finalize re-zeroes after reading,
// so every call (correctness run and each graph replay) starts from zero.
__device__ unsigned int g_counts[NHIST];
__device__ unsigned int g_ticket;

__device__ __forceinline__ int bin_of(float x) {
    // TF histogram_fixed_width rule: clip(int(x*256), 0, 255), trunc toward zero
    int b = __float2int_rz(x * 256.0f);
    return max(0, min(255, b));
}

__global__ void __launch_bounds__(BLOCK_THREADS, 4)
hist_kernel(const float4* __restrict__ in4, int n4,
            const float* __restrict__ in, int n_total,
            float* __restrict__ out, float inv_total) {
    // Bank-privatized layout: counter (c, bin, col) at sh[(c*256+bin)*16 + col].
    // Bank = 16*(bin&1) + col  ->  only lanes l and l+16 can collide, max degree 2.
    __shared__ unsigned int sh[NHIST * NCOL];   // 48 KB -> 4 CTAs/SM

    for (int i = threadIdx.x; i < NHIST * NCOL; i += BLOCK_THREADS)
        sh[i] = 0u;
    __syncthreads();

    const int stride = GRID_BLOCKS * BLOCK_THREADS;   // % 3 == 0
    int j0 = blockIdx.x * BLOCK_THREADS + threadIdx.x;

    // Channel phase of this thread (loop-invariant since stride % 3 == 0).
    // float4 j holds elements with channels c0, c0+1, c0+2, c0 (4 == 1 mod 3).
    int c0 = j0 % 3;
    int c1 = c0 + 1; if (c1 == 3) c1 = 0;
    int c2 = c1 + 1; if (c2 == 3) c2 = 0;
    unsigned int* col = sh + (threadIdx.x & (NCOL - 1));
    unsigned int* p0 = col + c0 * (NBINS * NCOL);
    unsigned int* p1 = col + c1 * (NBINS * NCOL);
    unsigned int* p2 = col + c2 * (NBINS * NCOL);

    // Main loop: 4 front-batched loads (MLP_p1 = 4), then 16 shared atomics.
    int j = j0;
    for (; j + 3 * stride < n4; j += 4 * stride) {
        float4 a = in4[j];
        float4 b = in4[j + stride];
        float4 c = in4[j + 2 * stride];
        float4 d = in4[j + 3 * stride];

        atomicAdd(&p0[bin_of(a.x) * NCOL], 1u);
        atomicAdd(&p1[bin_of(a.y) * NCOL], 1u);
        atomicAdd(&p2[bin_of(a.z) * NCOL], 1u);
        atomicAdd(&p0[bin_of(a.w) * NCOL], 1u);

        atomicAdd(&p0[bin_of(b.x) * NCOL], 1u);
        atomicAdd(&p1[bin_of(b.y) * NCOL], 1u);
        atomicAdd(&p2[bin_of(b.z) * NCOL], 1u);
        atomicAdd(&p0[bin_of(b.w) * NCOL], 1u);

        atomicAdd(&p0[bin_of(c.x) * NCOL], 1u);
        atomicAdd(&p1[bin_of(c.y) * NCOL], 1u);
        atomicAdd(&p2[bin_of(c.z) * NCOL], 1u);
        atomicAdd(&p0[bin_of(c.w) * NCOL], 1u);

        atomicAdd(&p0[bin_of(d.x) * NCOL], 1u);
        atomicAdd(&p1[bin_of(d.y) * NCOL], 1u);
        atomicAdd(&p2[bin_of(d.z) * NCOL], 1u);
        atomicAdd(&p0[bin_of(d.w) * NCOL], 1u);
    }
    // Remainder (up to 3 strided iterations)
    for (; j < n4; j += stride) {
        float4 a = in4[j];
        atomicAdd(&p0[bin_of(a.x) * NCOL], 1u);
        atomicAdd(&p1[bin_of(a.y) * NCOL], 1u);
        atomicAdd(&p2[bin_of(a.z) * NCOL], 1u);
        atomicAdd(&p0[bin_of(a.w) * NCOL], 1u);
    }

    // Scalar tail (n_total % 4 != 0) — block 0 only (no-op for this shape)
    if (blockIdx.x == 0) {
        for (int i = n4 * 4 + threadIdx.x; i < n_total; i += BLOCK_THREADS) {
            int c = i % 3;
            atomicAdd(&sh[(c * NBINS + bin_of(in[i])) * NCOL
                          + (threadIdx.x & (NCOL - 1))], 1u);
        }
    }

    __syncthreads();

    // Reduce the 16 columns per bin, publish block partial to L2 counters
    for (int i = threadIdx.x; i < NHIST; i += BLOCK_THREADS) {
        unsigned int s = 0u;
        #pragma unroll
        for (int c = 0; c < NCOL; c++) s += sh[i * NCOL + c];
        if (s) atomicAdd(&g_counts[i], s);
    }

    // Fused finalize: last block to arrive normalizes and resets state.
    __threadfence();
    __shared__ unsigned int ticket;
    if (threadIdx.x == 0) ticket = atomicAdd(&g_ticket, 1u);
    __syncthreads();
    if (ticket == GRID_BLOCKS - 1) {
        for (int i = threadIdx.x; i < NHIST; i += BLOCK_THREADS) {
            unsigned int s = atomicAdd(&g_counts[i], 0u);   // coherent read
            g_counts[i] = 0u;                               // reset for next call
            int c   = i >> 8;
            int bin = i & (NBINS - 1);
            // reference output is hist.T -> [nbins, 3] row-major
            out[bin * NCH + c] = (float)s * inv_total;
        }
        if (threadIdx.x == 0) g_ticket = 0u;                // reset ticket
    }
}

extern "C" void kernel_launch(void* const* d_in, const int* in_sizes, int n_in,
                              void* d_out, int out_size) {
    const float* in = (const float*)d_in[0];
    int n = in_sizes[0];                 // 64*512*512*3 = 50,331,648
    int n4 = n / 4;
    float inv_total = 1.0f / (float)(n / 3);   // per-channel pixel count (exact)

    hist_kernel<<<GRID_BLOCKS, BLOCK_THREADS>>>((const float4*)in, n4, in, n,
                                                (float*)d_out, inv_total);
}